// round 10
// baseline (speedup 1.0000x reference)
#include <cuda_runtime.h>
#include <cuda_bf16.h>

#define N_NODES 100000
#define N_EDGES 1600000
#define IN_DIM  512
#define OUT_DIM 32
#define KSTEPS  10
#define ALPHA   0.1f

typedef unsigned long long ull;

// ---------------- device scratch (allocation-free) ----------------
__device__ float  g_h[N_NODES * OUT_DIM];      // 12.8 MB  (projection)
__device__ float  g_z[N_NODES * OUT_DIM];      // 12.8 MB  scaled-z ping
__device__ float  g_z2[N_NODES * OUT_DIM];     // 12.8 MB  scaled-z pong
__device__ int    g_src[N_EDGES];
__device__ int    g_dst[N_EDGES];
__device__ int    g_deg[N_NODES];
__device__ float  g_dinv[N_NODES];
__device__ int    g_rowptr[N_NODES + 1];
__device__ int    g_cursor[N_NODES];
__device__ int    g_pidx[N_EDGES];             // CSR col index (src), 4B/edge
__device__ int    g_partial[128];
__device__ int    g_is64;

// ---------------- init degrees + dtype sniff (fused) ----------------
__global__ void k_init_detect(const int* __restrict__ e32) {
    int i = blockIdx.x * blockDim.x + threadIdx.x;
    if (i < N_NODES) g_deg[i] = 1;   // self loop
    if (i == 0) {
        int ok = 1;
#pragma unroll
        for (int q = 1; q < 64; q += 2)
            if (e32[q] != 0) ok = 0;
        g_is64 = ok;
    }
}

// ---------------- decode edges + count in-degrees (fused) ----------------
__global__ void k_decode_count(const void* __restrict__ ei) {
    int e = blockIdx.x * blockDim.x + threadIdx.x;
    if (e >= N_EDGES) return;
    int s, d;
    if (g_is64) {
        const long long* p = (const long long*)ei;
        s = (int)p[e];
        d = (int)p[N_EDGES + e];
    } else {
        const int* p = (const int*)ei;
        s = p[e];
        d = p[N_EDGES + e];
    }
    if (s < 0) s = 0; if (s >= N_NODES) s = N_NODES - 1;
    if (d < 0) d = 0; if (d >= N_NODES) d = N_NODES - 1;
    g_src[e] = s;
    g_dst[e] = d;
    atomicAdd(&g_deg[d], 1);
}

// ---------------- dinv = rsqrt(deg) + per-block sums of (deg-1) (fused) ----------------
__global__ void k_dinv_blocksum() {
    int base = blockIdx.x * 1024;
    int t = threadIdx.x;
    int s = 0;
#pragma unroll
    for (int i = 0; i < 4; i++) {
        int idx = base + t * 4 + i;
        if (idx < N_NODES) {
            int d = g_deg[idx];
            g_dinv[idx] = rsqrtf((float)d);
            s += d - 1;
        }
    }
#pragma unroll
    for (int o = 16; o; o >>= 1) s += __shfl_down_sync(0xffffffffu, s, o);
    __shared__ int ws[8];
    if ((t & 31) == 0) ws[t >> 5] = s;
    __syncthreads();
    if (t == 0) {
        int tot = 0;
#pragma unroll
        for (int i = 0; i < 8; i++) tot += ws[i];
        g_partial[blockIdx.x] = tot;
    }
}

// ---------------- exclusive scan of block sums (1 warp) ----------------
__global__ void k_scanpartial(int nb) {
    int lane = threadIdx.x;
    int v[4];
    int tsum = 0;
#pragma unroll
    for (int i = 0; i < 4; i++) {
        int idx = lane * 4 + i;
        v[i] = (idx < nb) ? g_partial[idx] : 0;
        tsum += v[i];
    }
    int inc = tsum;
#pragma unroll
    for (int o = 1; o < 32; o <<= 1) {
        int y = __shfl_up_sync(0xffffffffu, inc, o);
        if (lane >= o) inc += y;
    }
    int run = inc - tsum;   // exclusive
#pragma unroll
    for (int i = 0; i < 4; i++) {
        int idx = lane * 4 + i;
        if (idx < nb) { g_partial[idx] = run; run += v[i]; }
    }
    int total = __shfl_sync(0xffffffffu, inc, 31);
    if (lane == 0) g_rowptr[N_NODES] = total;
}

// ---------------- full exclusive scan -> rowptr & cursor ----------------
__global__ void k_blockscan() {
    int t = threadIdx.x;
    int base = blockIdx.x * 1024 + t * 4;
    int v[4];
    int tsum = 0;
#pragma unroll
    for (int i = 0; i < 4; i++) {
        int idx = base + i;
        v[i] = (idx < N_NODES) ? (g_deg[idx] - 1) : 0;
        tsum += v[i];
    }
    int lane = t & 31, warp = t >> 5;
    int inc = tsum;
#pragma unroll
    for (int o = 1; o < 32; o <<= 1) {
        int y = __shfl_up_sync(0xffffffffu, inc, o);
        if (lane >= o) inc += y;
    }
    int excl = inc - tsum;
    __shared__ int wtot[8];
    if (lane == 31) wtot[warp] = inc;
    __syncthreads();
    if (t == 0) {
        int acc = 0;
#pragma unroll
        for (int i = 0; i < 8; i++) { int x = wtot[i]; wtot[i] = acc; acc += x; }
    }
    __syncthreads();
    int off = g_partial[blockIdx.x] + wtot[warp] + excl;
#pragma unroll
    for (int i = 0; i < 4; i++) {
        int idx = base + i;
        if (idx < N_NODES) { g_rowptr[idx] = off; g_cursor[idx] = off; off += v[i]; }
    }
}

// ---------------- dense projection: h = x @ W^T + b ; zs0 = dinv * h ----------------
// f32x2 paired over ROW pairs (not col pairs): x operand (x[r],x[r+1]) comes
// non-duplicated from xT (adjacent rows contiguous at fixed k); W operand is
// (Wc,Wc) from a small duplicated table. Thread tile 16 rows x 4 cols:
// per kk = 4 x LDS.128 + 2 W LDS.128 per 32 FFMA2 (vs 3 per 8 previously).
// Block: 8 warps, each 64 rows x 32 cols -> 512 rows/block. kc = 16.
__global__ __launch_bounds__(256) void k_gemm(const float* __restrict__ x,
                                              const float* __restrict__ W,
                                              const float* __restrict__ b) {
    __shared__ alignas(16) float xT[16][520];   // [kk][row] 33.3 KB
    __shared__ alignas(16) float Wd[16][64];    // [kk][2j(+1)] dup, 4 KB

    int t    = threadIdx.x;
    int lane = t & 31;
    int warp = t >> 5;
    int rg   = lane >> 3;      // row group 0..3 (16 rows each)
    int cg   = lane & 7;       // col group 0..7 (4 cols each)
    int row0 = blockIdx.x * 512;

    ull acc[8][4];             // [row-pair][col]
#pragma unroll
    for (int p = 0; p < 8; p++)
#pragma unroll
        for (int c = 0; c < 4; c++) acc[p][c] = 0ull;

    const float* xb = &xT[0][0] + warp * 64 + rg * 16;
    const float* wb = &Wd[0][0] + 8 * cg;

    for (int chunk = 0; chunk < 32; chunk++) {
        int k0 = chunk * 16;
        __syncthreads();
        // stage Wd: 32 cols x 16 kk, duplicated
#pragma unroll
        for (int it = 0; it < 2; it++) {
            int idx = t + it * 256;      // 0..511
            int j  = idx >> 4;           // 0..31
            int kk = idx & 15;
            float wv = W[j * IN_DIM + k0 + kk];
            Wd[kk][2 * j]     = wv;
            Wd[kk][2 * j + 1] = wv;
        }
        // stage xT: 512 rows x 16 kk
#pragma unroll
        for (int it = 0; it < 8; it++) {
            int idx = t + it * 256;      // 0..2047
            int row = idx >> 2;          // 0..511
            int q   = idx & 3;           // which float4 of the 16 kk
            int gr  = row0 + row;
            if (gr >= N_NODES) gr = N_NODES - 1;
            float4 xv = *(const float4*)&x[(size_t)gr * IN_DIM + k0 + q * 4];
            xT[q * 4 + 0][row] = xv.x;
            xT[q * 4 + 1][row] = xv.y;
            xT[q * 4 + 2][row] = xv.z;
            xT[q * 4 + 3][row] = xv.w;
        }
        __syncthreads();

#pragma unroll 4
        for (int kk = 0; kk < 16; kk++) {
            const float* xr = xb + kk * 520;
            const float* wr = wb + kk * 64;
            ulonglong2 xa = *(const ulonglong2*)(xr);        // pairs 0,1
            ulonglong2 xbv = *(const ulonglong2*)(xr + 4);   // pairs 2,3
            ulonglong2 xc = *(const ulonglong2*)(xr + 8);    // pairs 4,5
            ulonglong2 xd = *(const ulonglong2*)(xr + 12);   // pairs 6,7
            ulonglong2 w0 = *(const ulonglong2*)(wr);        // (c0c0, c1c1)
            ulonglong2 w1 = *(const ulonglong2*)(wr + 4);    // (c2c2, c3c3)
            ull xp[8] = {xa.x, xa.y, xbv.x, xbv.y, xc.x, xc.y, xd.x, xd.y};
            ull wp[4] = {w0.x, w0.y, w1.x, w1.y};
#pragma unroll
            for (int p = 0; p < 8; p++) {
                asm("fma.rn.f32x2 %0, %1, %2, %0;" : "+l"(acc[p][0]) : "l"(xp[p]), "l"(wp[0]));
                asm("fma.rn.f32x2 %0, %1, %2, %0;" : "+l"(acc[p][1]) : "l"(xp[p]), "l"(wp[1]));
                asm("fma.rn.f32x2 %0, %1, %2, %0;" : "+l"(acc[p][2]) : "l"(xp[p]), "l"(wp[2]));
                asm("fma.rn.f32x2 %0, %1, %2, %0;" : "+l"(acc[p][3]) : "l"(xp[p]), "l"(wp[3]));
            }
        }
    }

    float4 bv = *(const float4*)&b[4 * cg];
#pragma unroll
    for (int p = 0; p < 8; p++) {
        int r = row0 + warp * 64 + rg * 16 + 2 * p;   // row pair (r, r+1)
        float lo0, hi0, lo1, hi1, lo2, hi2, lo3, hi3;
        asm("mov.b64 {%0, %1}, %2;" : "=f"(lo0), "=f"(hi0) : "l"(acc[p][0]));
        asm("mov.b64 {%0, %1}, %2;" : "=f"(lo1), "=f"(hi1) : "l"(acc[p][1]));
        asm("mov.b64 {%0, %1}, %2;" : "=f"(lo2), "=f"(hi2) : "l"(acc[p][2]));
        asm("mov.b64 {%0, %1}, %2;" : "=f"(lo3), "=f"(hi3) : "l"(acc[p][3]));
        if (r < N_NODES) {
            float4 hv = make_float4(lo0 + bv.x, lo1 + bv.y, lo2 + bv.z, lo3 + bv.w);
            *(float4*)&g_h[(size_t)r * 32 + 4 * cg] = hv;
            float di = g_dinv[r];
            *(float4*)&g_z[(size_t)r * 32 + 4 * cg] =
                make_float4(hv.x * di, hv.y * di, hv.z * di, hv.w * di);
        }
        if (r + 1 < N_NODES) {
            float4 hv = make_float4(hi0 + bv.x, hi1 + bv.y, hi2 + bv.z, hi3 + bv.w);
            *(float4*)&g_h[(size_t)(r + 1) * 32 + 4 * cg] = hv;
            float di = g_dinv[r + 1];
            *(float4*)&g_z[(size_t)(r + 1) * 32 + 4 * cg] =
                make_float4(hv.x * di, hv.y * di, hv.z * di, hv.w * di);
        }
    }
}

// ---------------- CSR scatter (index only) ----------------
__global__ void k_scatter() {
    int e = blockIdx.x * blockDim.x + threadIdx.x;
    if (e >= N_EDGES) return;
    int s = g_src[e];
    int d = g_dst[e];
    int pos = atomicAdd(&g_cursor[d], 1);
    g_pidx[pos] = s;
}

// ---------------- propagation step (pull, warp per node, paired float2 gathers) ----
__global__ __launch_bounds__(256) void k_prop(int srcSel, int finalStep, float* __restrict__ dout) {
    int gw   = (blockIdx.x * blockDim.x + threadIdx.x) >> 5;
    int lane = threadIdx.x & 31;
    int half = lane >> 4;     // 0: row A, 1: row B
    int hl   = lane & 15;     // float2 slot within row
    const float2* zin2 = (const float2*)((srcSel == 1) ? g_z : g_z2);
    float* zoutf = finalStep ? dout : ((srcSel == 1) ? (float*)g_z2 : (float*)g_z);

    int start = g_rowptr[gw];
    int end   = g_rowptr[gw + 1];

    float ax = 0.f, ay = 0.f, bx = 0.f, by = 0.f;
    for (int base = start; base < end; base += 32) {
        int m = end - base;
        if (m > 32) m = 32;
        int si = (lane < m) ? g_pidx[base + lane] : 0;
        int kk = 0;
        for (; kk + 16 <= m; kk += 16) {
            int s[8];
#pragma unroll
            for (int p = 0; p < 8; p++)
                s[p] = __shfl_sync(0xffffffffu, si, kk + 2 * p + half);
            float2 v[8];
#pragma unroll
            for (int p = 0; p < 8; p++)
                v[p] = zin2[(size_t)s[p] * 16 + hl];
#pragma unroll
            for (int p = 0; p < 8; p += 2) {
                ax += v[p].x;     ay += v[p].y;
                bx += v[p + 1].x; by += v[p + 1].y;
            }
        }
        for (; kk < m; kk += 2) {
            int idx2 = kk + half;
            int srcl = (idx2 < m) ? idx2 : kk;
            int s = __shfl_sync(0xffffffffu, si, srcl);
            float2 v = zin2[(size_t)s * 16 + hl];
            if (idx2 < m) { ax += v.x; ay += v.y; }
        }
    }
    float sx = ax + bx, sy = ay + by;
    sx += __shfl_xor_sync(0xffffffffu, sx, 16);
    sy += __shfl_xor_sync(0xffffffffu, sy, 16);

    float di = g_dinv[gw];
    float2 zself = zin2[(size_t)gw * 16 + hl];
    float2 hv    = ((const float2*)g_h)[(size_t)gw * 16 + hl];
    float znx = (1.0f - ALPHA) * (di * (sx + zself.x)) + ALPHA * hv.x;
    float zny = (1.0f - ALPHA) * (di * (sy + zself.y)) + ALPHA * hv.y;
    if (!finalStep) { znx *= di; zny *= di; }
    if (half == 0)
        *(float2*)&zoutf[(size_t)gw * 32 + 2 * hl] = make_float2(znx, zny);
}

// ---------------- host launcher ----------------
extern "C" void kernel_launch(void* const* d_in, const int* in_sizes, int n_in,
                              void* d_out, int out_size) {
    const float* x  = (const float*)d_in[0];
    const float* W  = (const float*)d_in[1];
    const float* b  = (const float*)d_in[2];
    const void*  ei = d_in[3];
    float* out = (float*)d_out;

    const int NB = (N_NODES + 1023) / 1024;   // 98

    k_init_detect<<<(N_NODES + 255) / 256, 256>>>((const int*)ei);   // 1
    k_decode_count<<<(N_EDGES + 255) / 256, 256>>>(ei);              // 2
    k_dinv_blocksum<<<NB, 256>>>();                                  // 3
    k_gemm<<<(N_NODES + 511) / 512, 256>>>(x, W, b);                 // 4 (ncu window)
    k_scanpartial<<<1, 32>>>(NB);                                    // 5
    k_blockscan<<<NB, 256>>>();                                      // 6
    k_scatter<<<N_EDGES / 256, 256>>>();                             // 7

    // 10 steps: zs ping-pongs g_z (srcSel=1) <-> g_z2 (srcSel=2); final writes dout.
    int srcSel = 1;
    for (int s = 1; s <= KSTEPS; s++) {
        k_prop<<<N_NODES * 32 / 256, 256>>>(srcSel, (s == KSTEPS) ? 1 : 0, out);
        srcSel = 3 - srcSel;
    }
}